// round 1
// baseline (speedup 1.0000x reference)
#include <cuda_runtime.h>
#include <cuda_bf16.h>
#include <math.h>
#include <stdint.h>

// Problem dims (fixed by the dataset)
#define BQ 64
#define SQ 512
#define DQ 768
#define CQ 512
#define MQ (BQ*SQ)   // 32768 tokens

// ---------------- scratch (device globals; no allocation allowed) ----------
__device__ __nv_bfloat16 g_Vn[(size_t)MQ * DQ];   // normalized V, bf16 (50 MB)
__device__ __nv_bfloat16 g_Ln[(size_t)CQ * DQ];   // normalized labels, bf16
__device__ unsigned      g_mkey[MQ];              // ordered-uint encoded row max
__device__ float         g_z[BQ * DQ];            // z vectors

// ordered-uint encoding for float atomicMax (handles negatives)
__device__ __forceinline__ unsigned enc_f(float f) {
    unsigned u = __float_as_uint(f);
    return (u & 0x80000000u) ? ~u : (u | 0x80000000u);
}
__device__ __forceinline__ float dec_f(unsigned u) {
    return (u & 0x80000000u) ? __uint_as_float(u & 0x7fffffffu)
                             : __uint_as_float(~u);
}

// ---------------- kernel 1/2: row-normalize (warp per row) -----------------
// mode 0: labels -> g_Ln ; mode 1: V -> g_Vn (+ init g_mkey)
__global__ void row_normalize_kernel(const float* __restrict__ in, int nrows, int mode) {
    int gw   = (blockIdx.x * blockDim.x + threadIdx.x) >> 5;
    int lane = threadIdx.x & 31;
    if (gw >= nrows) return;

    const float4* r = (const float4*)(in + (size_t)gw * DQ);
    float4 v[6];
    float ss = 0.f;
#pragma unroll
    for (int i = 0; i < 6; i++) {
        v[i] = r[lane + i * 32];
        ss += v[i].x * v[i].x + v[i].y * v[i].y + v[i].z * v[i].z + v[i].w * v[i].w;
    }
#pragma unroll
    for (int o = 16; o; o >>= 1) ss += __shfl_xor_sync(0xffffffffu, ss, o);
    float denom = fmaxf(sqrtf(ss), 1e-8f);
    float sc = 1.0f / denom;

    __nv_bfloat16* out = (mode ? g_Vn : g_Ln) + (size_t)gw * DQ;
#pragma unroll
    for (int i = 0; i < 6; i++) {
        int base = (lane + i * 32) * 4;
        __nv_bfloat162 p0 = __floats2bfloat162_rn(v[i].x * sc, v[i].y * sc);
        __nv_bfloat162 p1 = __floats2bfloat162_rn(v[i].z * sc, v[i].w * sc);
        uint2 pk;
        pk.x = *(unsigned*)&p0;
        pk.y = *(unsigned*)&p1;
        *(uint2*)(out + base) = pk;
    }
    if (mode && lane == 0) g_mkey[gw] = 0u;   // below every encoded real value
}

// ---------------- kernel 3: bf16 GEMM (Vn @ Ln^T) + row max ---------------
// CTA tile 128x128, BK=32, 8 warps (warp tile 64x32), mma.m16n8k16 bf16.
// smem stride 40 bf16 (80B) -> conflict-free fragment LDS.
__global__ __launch_bounds__(256, 2)
void gemm_rowmax_kernel() {
    __shared__ __align__(16) __nv_bfloat16 As[128][40];
    __shared__ __align__(16) __nv_bfloat16 Bs[128][40];
    __shared__ float rmax[128][4];

    const int bn = blockIdx.x;        // 0..3   (class tiles)
    const int bm = blockIdx.y;        // 0..255 (token tiles)
    const int t = threadIdx.x;
    const int lane = t & 31, warp = t >> 5;
    const int wr = warp & 1, wc = warp >> 1;
    const int wm0 = wr * 64, wn0 = wc * 32;
    const int g = lane >> 2, tq = lane & 3;

    float acc[4][4][4];
#pragma unroll
    for (int mi = 0; mi < 4; mi++)
#pragma unroll
        for (int ni = 0; ni < 4; ni++)
#pragma unroll
            for (int q = 0; q < 4; q++) acc[mi][ni][q] = 0.f;

    const size_t a_base = (size_t)(bm * 128) * DQ;
    const size_t b_base = (size_t)(bn * 128) * DQ;

    for (int k0 = 0; k0 < DQ; k0 += 32) {
#pragma unroll
        for (int i = 0; i < 2; i++) {
            int lin = t + i * 256;     // 0..511
            int row = lin >> 2;
            int cu  = lin & 3;
            *(uint4*)&As[row][cu * 8] =
                *(const uint4*)&g_Vn[a_base + (size_t)row * DQ + k0 + cu * 8];
            *(uint4*)&Bs[row][cu * 8] =
                *(const uint4*)&g_Ln[b_base + (size_t)row * DQ + k0 + cu * 8];
        }
        __syncthreads();

#pragma unroll
        for (int kk = 0; kk < 32; kk += 16) {
            unsigned af[4][4], bf[4][2];
#pragma unroll
            for (int mi = 0; mi < 4; mi++) {
                int r = wm0 + mi * 16 + g;
                int c = kk + tq * 2;
                af[mi][0] = *(const unsigned*)&As[r][c];
                af[mi][1] = *(const unsigned*)&As[r + 8][c];
                af[mi][2] = *(const unsigned*)&As[r][c + 8];
                af[mi][3] = *(const unsigned*)&As[r + 8][c + 8];
            }
#pragma unroll
            for (int ni = 0; ni < 4; ni++) {
                int n = wn0 + ni * 8 + g;
                int c = kk + tq * 2;
                bf[ni][0] = *(const unsigned*)&Bs[n][c];
                bf[ni][1] = *(const unsigned*)&Bs[n][c + 8];
            }
#pragma unroll
            for (int mi = 0; mi < 4; mi++)
#pragma unroll
                for (int ni = 0; ni < 4; ni++) {
                    asm volatile(
                        "mma.sync.aligned.m16n8k16.row.col.f32.bf16.bf16.f32 "
                        "{%0,%1,%2,%3}, {%4,%5,%6,%7}, {%8,%9}, {%0,%1,%2,%3};\n"
                        : "+f"(acc[mi][ni][0]), "+f"(acc[mi][ni][1]),
                          "+f"(acc[mi][ni][2]), "+f"(acc[mi][ni][3])
                        : "r"(af[mi][0]), "r"(af[mi][1]), "r"(af[mi][2]), "r"(af[mi][3]),
                          "r"(bf[ni][0]), "r"(bf[ni][1]));
                }
        }
        __syncthreads();
    }

    // per-row max over this 128-class tile
#pragma unroll
    for (int mi = 0; mi < 4; mi++) {
        float lo = -INFINITY, hi = -INFINITY;
#pragma unroll
        for (int ni = 0; ni < 4; ni++) {
            lo = fmaxf(lo, fmaxf(acc[mi][ni][0], acc[mi][ni][1]));
            hi = fmaxf(hi, fmaxf(acc[mi][ni][2], acc[mi][ni][3]));
        }
        lo = fmaxf(lo, __shfl_xor_sync(0xffffffffu, lo, 1));
        lo = fmaxf(lo, __shfl_xor_sync(0xffffffffu, lo, 2));
        hi = fmaxf(hi, __shfl_xor_sync(0xffffffffu, hi, 1));
        hi = fmaxf(hi, __shfl_xor_sync(0xffffffffu, hi, 2));
        if (tq == 0) {
            rmax[wm0 + mi * 16 + g][wc]     = lo;
            rmax[wm0 + mi * 16 + g + 8][wc] = hi;
        }
    }
    __syncthreads();
    if (t < 128) {
        float v = fmaxf(fmaxf(rmax[t][0], rmax[t][1]),
                        fmaxf(rmax[t][2], rmax[t][3]));
        atomicMax(&g_mkey[bm * 128 + t], enc_f(v));
    }
}

// ---------------- kernel 4: softmax over S + z = V^T beta ------------------
// grid (B, 4): each CTA recomputes softmax (cheap) and handles 192 d-columns
__global__ void softmax_z_kernel(const float* __restrict__ V, float* __restrict__ zout) {
    __shared__ float pbuf[SQ];
    __shared__ float redm[8], reds[8];
    const int b = blockIdx.x, ch = blockIdx.y;
    const int t = threadIdx.x;
    const int lane = t & 31, wid = t >> 5;

    float lm = -INFINITY;
    for (int s = t; s < SQ; s += 192) {
        float v = dec_f(g_mkey[b * SQ + s]);
        pbuf[s] = v;
        lm = fmaxf(lm, v);
    }
#pragma unroll
    for (int o = 16; o; o >>= 1) lm = fmaxf(lm, __shfl_xor_sync(0xffffffffu, lm, o));
    if (lane == 0) redm[wid] = lm;
    __syncthreads();
    float M = redm[0];
#pragma unroll
    for (int i = 1; i < 6; i++) M = fmaxf(M, redm[i]);

    float ls = 0.f;
    for (int s = t; s < SQ; s += 192) {
        float p = expf(pbuf[s] - M);
        pbuf[s] = p;
        ls += p;
    }
#pragma unroll
    for (int o = 16; o; o >>= 1) ls += __shfl_xor_sync(0xffffffffu, ls, o);
    if (lane == 0) reds[wid] = ls;
    __syncthreads();
    float S = 0.f;
#pragma unroll
    for (int i = 0; i < 6; i++) S += reds[i];
    float scale = 1.f / S;

    const int d = ch * 192 + t;           // blockDim.x == 192
    const float* Vb = V + (size_t)b * SQ * DQ + d;
    float a0 = 0.f, a1 = 0.f, a2 = 0.f, a3 = 0.f;
#pragma unroll 4
    for (int s = 0; s < SQ; s += 4) {
        a0 += pbuf[s + 0] * Vb[(size_t)(s + 0) * DQ];
        a1 += pbuf[s + 1] * Vb[(size_t)(s + 1) * DQ];
        a2 += pbuf[s + 2] * Vb[(size_t)(s + 2) * DQ];
        a3 += pbuf[s + 3] * Vb[(size_t)(s + 3) * DQ];
    }
    float zc = (a0 + a1 + a2 + a3) * scale;
    g_z[b * DQ + d] = zc;
    if (zout) zout[b * DQ + d] = zc;
}

// ---------------- kernel 5: out = z @ fc_w^T + fc_b ------------------------
// warp per (b, c)
__global__ void fc_kernel(const float* __restrict__ fc_w, const float* __restrict__ fc_b,
                          float* __restrict__ out) {
    const int t = threadIdx.x;
    const int lane = t & 31;
    const int gw = (blockIdx.x * blockDim.x + t) >> 5;
    if (gw >= BQ * CQ) return;
    const int b = gw >> 9;     // /512
    const int c = gw & 511;
    const float4* wr = (const float4*)(fc_w + (size_t)c * DQ);
    const float4* zr = (const float4*)(g_z + b * DQ);
    float acc = 0.f;
#pragma unroll
    for (int i = 0; i < 6; i++) {
        float4 wv = wr[lane + i * 32];
        float4 zv = zr[lane + i * 32];
        acc += wv.x * zv.x + wv.y * zv.y + wv.z * zv.z + wv.w * zv.w;
    }
#pragma unroll
    for (int o = 16; o; o >>= 1) acc += __shfl_xor_sync(0xffffffffu, acc, o);
    if (lane == 0) out[b * CQ + c] = acc + fc_b[c];
}

// ---------------- launch ----------------------------------------------------
extern "C" void kernel_launch(void* const* d_in, const int* in_sizes, int n_in,
                              void* d_out, int out_size) {
    const float* V  = (const float*)d_in[0];
    const float* L  = (const float*)d_in[1];
    const float* fw = (const float*)d_in[2];
    const float* fb = (const float*)d_in[3];
    float* out = (float*)d_out;
    float* zout = (out_size >= BQ * CQ + BQ * DQ) ? (out + BQ * CQ) : nullptr;

    // 1. normalize labels -> g_Ln   (512 rows, warp/row)
    row_normalize_kernel<<<CQ / 8, 256>>>(L, CQ, 0);
    // 2. normalize V -> g_Vn + init g_mkey  (32768 rows)
    row_normalize_kernel<<<MQ / 8, 256>>>(V, MQ, 1);
    // 3. bf16 GEMM + row max
    gemm_rowmax_kernel<<<dim3(CQ / 128, MQ / 128), 256>>>();
    // 4. softmax + z (writes g_z and z half of d_out)
    softmax_z_kernel<<<dim3(BQ, 4), 192>>>(V, zout);
    // 5. fc head -> out half of d_out
    fc_kernel<<<(BQ * CQ * 32) / 256, 256>>>(fw, fb, out);
}

// round 2
// speedup vs baseline: 1.2073x; 1.2073x over previous
#include <cuda_runtime.h>
#include <cuda_bf16.h>
#include <math.h>
#include <stdint.h>

// Problem dims (fixed by the dataset)
#define BQ 64
#define SQ 512
#define DQ 768
#define CQ 512
#define MQ (BQ*SQ)   // 32768 tokens
#define ZCH 8        // s-chunks for partial z

// ---------------- scratch (device globals; no allocation allowed) ----------
__device__ __nv_bfloat16 g_Vn[(size_t)MQ * DQ];   // normalized V, bf16 (48 MB)
__device__ __nv_bfloat16 g_Ln[(size_t)CQ * DQ];   // normalized labels, bf16
__device__ unsigned      g_mkey[MQ];              // ordered-uint encoded row max
__device__ float         g_beta[MQ];              // softmax weights
__device__ float         g_zpart[BQ * ZCH * DQ];  // partial z sums
__device__ float         g_z[BQ * DQ];            // z vectors

// ordered-uint encoding for float atomicMax (handles negatives)
__device__ __forceinline__ unsigned enc_f(float f) {
    unsigned u = __float_as_uint(f);
    return (u & 0x80000000u) ? ~u : (u | 0x80000000u);
}
__device__ __forceinline__ float dec_f(unsigned u) {
    return (u & 0x80000000u) ? __uint_as_float(u & 0x7fffffffu)
                             : __uint_as_float(~u);
}

// cp.async helpers
__device__ __forceinline__ void cpa16(void* smem, const void* g) {
    unsigned s = (unsigned)__cvta_generic_to_shared(smem);
    asm volatile("cp.async.cg.shared.global [%0], [%1], 16;\n" :: "r"(s), "l"(g));
}
#define CP_COMMIT() asm volatile("cp.async.commit_group;\n" ::: "memory")
#define CP_WAIT(n)  asm volatile("cp.async.wait_group %0;\n" :: "n"(n) : "memory")

// ---------------- kernel 1/2: row-normalize (warp per row) -----------------
// mode 0: labels -> g_Ln ; mode 1: V -> g_Vn (+ init g_mkey)
__global__ void row_normalize_kernel(const float* __restrict__ in, int nrows, int mode) {
    int gw   = (blockIdx.x * blockDim.x + threadIdx.x) >> 5;
    int lane = threadIdx.x & 31;
    if (gw >= nrows) return;

    const float4* r = (const float4*)(in + (size_t)gw * DQ);
    float4 v[6];
    float ss = 0.f;
#pragma unroll
    for (int i = 0; i < 6; i++) {
        v[i] = r[lane + i * 32];
        ss += v[i].x * v[i].x + v[i].y * v[i].y + v[i].z * v[i].z + v[i].w * v[i].w;
    }
#pragma unroll
    for (int o = 16; o; o >>= 1) ss += __shfl_xor_sync(0xffffffffu, ss, o);
    float denom = fmaxf(sqrtf(ss), 1e-8f);
    float sc = 1.0f / denom;

    __nv_bfloat16* out = (mode ? g_Vn : g_Ln) + (size_t)gw * DQ;
#pragma unroll
    for (int i = 0; i < 6; i++) {
        int base = (lane + i * 32) * 4;
        __nv_bfloat162 p0 = __floats2bfloat162_rn(v[i].x * sc, v[i].y * sc);
        __nv_bfloat162 p1 = __floats2bfloat162_rn(v[i].z * sc, v[i].w * sc);
        uint2 pk;
        pk.x = *(unsigned*)&p0;
        pk.y = *(unsigned*)&p1;
        *(uint2*)(out + base) = pk;
    }
    if (mode && lane == 0) g_mkey[gw] = 0u;   // below every encoded real value
}

// ---------------- kernel 3: bf16 GEMM (Vn @ Ln^T) + row max ---------------
// CTA tile 128x128, BK=32, 8 warps (warp tile 64x32), mma.m16n8k16 bf16.
// 2-stage cp.async double buffer. smem stride 40 bf16 -> conflict-free LDS.
__global__ __launch_bounds__(256, 2)
void gemm_rowmax_kernel() {
    __shared__ __align__(16) __nv_bfloat16 As[2][128][40];
    __shared__ __align__(16) __nv_bfloat16 Bs[2][128][40];
    __shared__ float rmax[128][4];

    const int bn = blockIdx.x;        // 0..3   (class tiles)
    const int bm = blockIdx.y;        // 0..255 (token tiles)
    const int t = threadIdx.x;
    const int lane = t & 31, warp = t >> 5;
    const int wr = warp & 1, wc = warp >> 1;
    const int wm0 = wr * 64, wn0 = wc * 32;
    const int g = lane >> 2, tq = lane & 3;

    float acc[4][4][4];
#pragma unroll
    for (int mi = 0; mi < 4; mi++)
#pragma unroll
        for (int ni = 0; ni < 4; ni++)
#pragma unroll
            for (int q = 0; q < 4; q++) acc[mi][ni][q] = 0.f;

    const size_t a_base = (size_t)(bm * 128) * DQ;
    const size_t b_base = (size_t)(bn * 128) * DQ;

    // thread -> (row, 16B-chunk) mapping for loads: 512 chunks per matrix
    const int r0 = (t + 0)   >> 2, c0 = (t + 0)   & 3;
    const int r1 = (t + 256) >> 2, c1 = (t + 256) & 3;

    auto load_stage = [&](int st, int k0) {
        cpa16(&As[st][r0][c0 * 8], &g_Vn[a_base + (size_t)r0 * DQ + k0 + c0 * 8]);
        cpa16(&As[st][r1][c1 * 8], &g_Vn[a_base + (size_t)r1 * DQ + k0 + c1 * 8]);
        cpa16(&Bs[st][r0][c0 * 8], &g_Ln[b_base + (size_t)r0 * DQ + k0 + c0 * 8]);
        cpa16(&Bs[st][r1][c1 * 8], &g_Ln[b_base + (size_t)r1 * DQ + k0 + c1 * 8]);
        CP_COMMIT();
    };

    load_stage(0, 0);

    const int NK = DQ / 32;           // 24
    for (int kt = 0; kt < NK; kt++) {
        const int cur = kt & 1;
        if (kt + 1 < NK) {
            load_stage(cur ^ 1, (kt + 1) * 32);
            CP_WAIT(1);
        } else {
            CP_WAIT(0);
        }
        __syncthreads();

#pragma unroll
        for (int kk = 0; kk < 32; kk += 16) {
            unsigned af[4][4], bf[4][2];
#pragma unroll
            for (int mi = 0; mi < 4; mi++) {
                int r = wm0 + mi * 16 + g;
                int c = kk + tq * 2;
                af[mi][0] = *(const unsigned*)&As[cur][r][c];
                af[mi][1] = *(const unsigned*)&As[cur][r + 8][c];
                af[mi][2] = *(const unsigned*)&As[cur][r][c + 8];
                af[mi][3] = *(const unsigned*)&As[cur][r + 8][c + 8];
            }
#pragma unroll
            for (int ni = 0; ni < 4; ni++) {
                int n = wn0 + ni * 8 + g;
                int c = kk + tq * 2;
                bf[ni][0] = *(const unsigned*)&Bs[cur][n][c];
                bf[ni][1] = *(const unsigned*)&Bs[cur][n][c + 8];
            }
#pragma unroll
            for (int mi = 0; mi < 4; mi++)
#pragma unroll
                for (int ni = 0; ni < 4; ni++) {
                    asm volatile(
                        "mma.sync.aligned.m16n8k16.row.col.f32.bf16.bf16.f32 "
                        "{%0,%1,%2,%3}, {%4,%5,%6,%7}, {%8,%9}, {%0,%1,%2,%3};\n"
                        : "+f"(acc[mi][ni][0]), "+f"(acc[mi][ni][1]),
                          "+f"(acc[mi][ni][2]), "+f"(acc[mi][ni][3])
                        : "r"(af[mi][0]), "r"(af[mi][1]), "r"(af[mi][2]), "r"(af[mi][3]),
                          "r"(bf[ni][0]), "r"(bf[ni][1]));
                }
        }
        __syncthreads();   // protect stage 'cur' before it is refilled next iter
    }

    // per-row max over this 128-class tile
#pragma unroll
    for (int mi = 0; mi < 4; mi++) {
        float lo = -INFINITY, hi = -INFINITY;
#pragma unroll
        for (int ni = 0; ni < 4; ni++) {
            lo = fmaxf(lo, fmaxf(acc[mi][ni][0], acc[mi][ni][1]));
            hi = fmaxf(hi, fmaxf(acc[mi][ni][2], acc[mi][ni][3]));
        }
        lo = fmaxf(lo, __shfl_xor_sync(0xffffffffu, lo, 1));
        lo = fmaxf(lo, __shfl_xor_sync(0xffffffffu, lo, 2));
        hi = fmaxf(hi, __shfl_xor_sync(0xffffffffu, hi, 1));
        hi = fmaxf(hi, __shfl_xor_sync(0xffffffffu, hi, 2));
        if (tq == 0) {
            rmax[wm0 + mi * 16 + g][wc]     = lo;
            rmax[wm0 + mi * 16 + g + 8][wc] = hi;
        }
    }
    __syncthreads();
    if (t < 128) {
        float v = fmaxf(fmaxf(rmax[t][0], rmax[t][1]),
                        fmaxf(rmax[t][2], rmax[t][3]));
        atomicMax(&g_mkey[bm * 128 + t], enc_f(v));
    }
}

// ---------------- kernel 4a: softmax over S -> g_beta ----------------------
// one CTA of 512 threads per batch
__global__ void beta_kernel() {
    __shared__ float red[16];
    const int b = blockIdx.x;
    const int t = threadIdx.x;
    const int lane = t & 31, wid = t >> 5;

    float m = dec_f(g_mkey[b * SQ + t]);
    float lm = m;
#pragma unroll
    for (int o = 16; o; o >>= 1) lm = fmaxf(lm, __shfl_xor_sync(0xffffffffu, lm, o));
    if (lane == 0) red[wid] = lm;
    __syncthreads();
    float M = red[0];
#pragma unroll
    for (int i = 1; i < 16; i++) M = fmaxf(M, red[i]);
    __syncthreads();

    float p = expf(m - M);
    float ls = p;
#pragma unroll
    for (int o = 16; o; o >>= 1) ls += __shfl_xor_sync(0xffffffffu, ls, o);
    if (lane == 0) red[wid] = ls;
    __syncthreads();
    float S = 0.f;
#pragma unroll
    for (int i = 0; i < 16; i++) S += red[i];

    g_beta[b * SQ + t] = p / S;
}

// ---------------- kernel 4b: partial z sums (row-wise coalesced V reads) ---
// grid (B, ZCH), 256 threads; CTA handles 64 s-rows, 3 d-cols per thread
__global__ void zpart_kernel(const float* __restrict__ V) {
    __shared__ float bsm[SQ / ZCH];
    const int b = blockIdx.x, ch = blockIdx.y;
    const int t = threadIdx.x;
    constexpr int RS = SQ / ZCH;   // 64 rows per chunk

    if (t < RS) bsm[t] = g_beta[b * SQ + ch * RS + t];
    __syncthreads();

    const float* Vb = V + ((size_t)b * SQ + ch * RS) * DQ;
    float a0 = 0.f, a1 = 0.f, a2 = 0.f;
#pragma unroll 4
    for (int r = 0; r < RS; r++) {
        float be = bsm[r];
        const float* row = Vb + (size_t)r * DQ;
        a0 += be * row[t];
        a1 += be * row[t + 256];
        a2 += be * row[t + 512];
    }
    float* zp = g_zpart + (size_t)(b * ZCH + ch) * DQ;
    zp[t]       = a0;
    zp[t + 256] = a1;
    zp[t + 512] = a2;
}

// ---------------- kernel 4c: combine partials -> z -------------------------
__global__ void zcombine_kernel(float* __restrict__ zout) {
    const int b = blockIdx.x;
    const int t = threadIdx.x;   // 256
#pragma unroll
    for (int j = 0; j < 3; j++) {
        int d = t + j * 256;
        float s = 0.f;
#pragma unroll
        for (int c = 0; c < ZCH; c++) s += g_zpart[(size_t)(b * ZCH + c) * DQ + d];
        g_z[b * DQ + d] = s;
        if (zout) zout[b * DQ + d] = s;
    }
}

// ---------------- kernel 5: out = z @ fc_w^T + fc_b ------------------------
// warp per (b, c)
__global__ void fc_kernel(const float* __restrict__ fc_w, const float* __restrict__ fc_b,
                          float* __restrict__ out) {
    const int t = threadIdx.x;
    const int lane = t & 31;
    const int gw = (blockIdx.x * blockDim.x + t) >> 5;
    if (gw >= BQ * CQ) return;
    const int b = gw >> 9;     // /512
    const int c = gw & 511;
    const float4* wr = (const float4*)(fc_w + (size_t)c * DQ);
    const float4* zr = (const float4*)(g_z + b * DQ);
    float acc = 0.f;
#pragma unroll
    for (int i = 0; i < 6; i++) {
        float4 wv = wr[lane + i * 32];
        float4 zv = zr[lane + i * 32];
        acc += wv.x * zv.x + wv.y * zv.y + wv.z * zv.z + wv.w * zv.w;
    }
#pragma unroll
    for (int o = 16; o; o >>= 1) acc += __shfl_xor_sync(0xffffffffu, acc, o);
    if (lane == 0) out[b * CQ + c] = acc + fc_b[c];
}

// ---------------- launch ----------------------------------------------------
extern "C" void kernel_launch(void* const* d_in, const int* in_sizes, int n_in,
                              void* d_out, int out_size) {
    const float* V  = (const float*)d_in[0];
    const float* L  = (const float*)d_in[1];
    const float* fw = (const float*)d_in[2];
    const float* fb = (const float*)d_in[3];
    float* out = (float*)d_out;
    float* zout = (out_size >= BQ * CQ + BQ * DQ) ? (out + BQ * CQ) : nullptr;

    // 1. normalize labels -> g_Ln   (512 rows, warp/row)
    row_normalize_kernel<<<CQ / 8, 256>>>(L, CQ, 0);
    // 2. normalize V -> g_Vn + init g_mkey  (32768 rows)
    row_normalize_kernel<<<MQ / 8, 256>>>(V, MQ, 1);
    // 3. bf16 GEMM + row max (cp.async double-buffered)
    gemm_rowmax_kernel<<<dim3(CQ / 128, MQ / 128), 256>>>();
    // 4. softmax -> beta ; partial z ; combine
    beta_kernel<<<BQ, SQ>>>();
    zpart_kernel<<<dim3(BQ, ZCH), 256>>>(V);
    zcombine_kernel<<<BQ, 256>>>(zout);
    // 5. fc head -> out half of d_out
    fc_kernel<<<(BQ * CQ * 32) / 256, 256>>>(fw, fb, out);
}

// round 4
// speedup vs baseline: 1.3205x; 1.0938x over previous
#include <cuda_runtime.h>
#include <cuda_bf16.h>
#include <math.h>
#include <stdint.h>

// Problem dims (fixed by the dataset)
#define BQ 64
#define SQ 512
#define DQ 768
#define CQ 512
#define MQ (BQ*SQ)   // 32768 tokens
#define ZCH 8        // s-chunks for partial z

// ---------------- scratch (device globals; no allocation allowed) ----------
__device__ __nv_bfloat16 g_Vn[(size_t)MQ * DQ];   // normalized V, bf16 (48 MB)
__device__ __nv_bfloat16 g_Ln[(size_t)CQ * DQ];   // normalized labels, bf16
__device__ unsigned      g_mkey[MQ];              // ordered-uint encoded row max
__device__ float         g_beta[MQ];              // softmax weights
__device__ float         g_zpart[BQ * ZCH * DQ];  // partial z sums
__device__ float         g_z[BQ * DQ];            // z vectors

// ordered-uint encoding for float atomicMax (handles negatives)
__device__ __forceinline__ unsigned enc_f(float f) {
    unsigned u = __float_as_uint(f);
    return (u & 0x80000000u) ? ~u : (u | 0x80000000u);
}
__device__ __forceinline__ float dec_f(unsigned u) {
    return (u & 0x80000000u) ? __uint_as_float(u & 0x7fffffffu)
                             : __uint_as_float(~u);
}

// cp.async helpers
__device__ __forceinline__ void cpa16(void* smem, const void* g) {
    unsigned s = (unsigned)__cvta_generic_to_shared(smem);
    asm volatile("cp.async.cg.shared.global [%0], [%1], 16;\n" :: "r"(s), "l"(g));
}
#define CP_COMMIT() asm volatile("cp.async.commit_group;\n" ::: "memory")
#define CP_WAIT(n)  asm volatile("cp.async.wait_group %0;\n" :: "n"(n) : "memory")

// ---------------- kernel 1/2: row-normalize (warp per row) -----------------
__global__ void row_normalize_kernel(const float* __restrict__ in, int nrows, int mode) {
    int gw   = (blockIdx.x * blockDim.x + threadIdx.x) >> 5;
    int lane = threadIdx.x & 31;
    if (gw >= nrows) return;

    const float4* r = (const float4*)(in + (size_t)gw * DQ);
    float4 v[6];
    float ss = 0.f;
#pragma unroll
    for (int i = 0; i < 6; i++) {
        v[i] = r[lane + i * 32];
        ss += v[i].x * v[i].x + v[i].y * v[i].y + v[i].z * v[i].z + v[i].w * v[i].w;
    }
#pragma unroll
    for (int o = 16; o; o >>= 1) ss += __shfl_xor_sync(0xffffffffu, ss, o);
    float denom = fmaxf(sqrtf(ss), 1e-8f);
    float sc = 1.0f / denom;

    __nv_bfloat16* out = (mode ? g_Vn : g_Ln) + (size_t)gw * DQ;
#pragma unroll
    for (int i = 0; i < 6; i++) {
        int base = (lane + i * 32) * 4;
        __nv_bfloat162 p0 = __floats2bfloat162_rn(v[i].x * sc, v[i].y * sc);
        __nv_bfloat162 p1 = __floats2bfloat162_rn(v[i].z * sc, v[i].w * sc);
        uint2 pk;
        pk.x = *(unsigned*)&p0;
        pk.y = *(unsigned*)&p1;
        *(uint2*)(out + base) = pk;
    }
    if (mode && lane == 0) g_mkey[gw] = 0u;
}

// ---------------- kernel 3: bf16 GEMM (Vn @ Ln^T) + row max ---------------
// CTA 128x128, BK=32, 4 warps (warp tile 64x64), 3-stage cp.async pipeline,
// one __syncthreads per BK tile. smem stride 40 bf16 -> conflict-free LDS.
#define GSTRIDE 40
#define GSTAGE  (128 * GSTRIDE)            // bf16 elems per matrix per stage
#define GK_SMEM (3 * 2 * GSTAGE * 2)       // bytes: 3 stages * (A+B) * 2B

__global__ __launch_bounds__(128, 2)
void gemm_rowmax_kernel() {
    extern __shared__ __nv_bfloat16 sm[];
    __nv_bfloat16* Asm = sm;                 // [3][128][40]
    __nv_bfloat16* Bsm = sm + 3 * GSTAGE;    // [3][128][40]
    __shared__ float rmax[128][2];

    const int bn = blockIdx.x;        // 0..3   (class tiles)
    const int bm = blockIdx.y;        // 0..255 (token tiles)
    const int t = threadIdx.x;        // 128 threads
    const int lane = t & 31, warp = t >> 5;
    const int wr = warp & 1, wc = warp >> 1;
    const int wm0 = wr * 64, wn0 = wc * 64;
    const int g = lane >> 2, tq = lane & 3;

    float acc[4][8][4];
#pragma unroll
    for (int mi = 0; mi < 4; mi++)
#pragma unroll
        for (int ni = 0; ni < 8; ni++)
#pragma unroll
            for (int q = 0; q < 4; q++) acc[mi][ni][q] = 0.f;

    const size_t a_base = (size_t)(bm * 128) * DQ;
    const size_t b_base = (size_t)(bn * 128) * DQ;

    // per-thread load mapping: 512 16B-chunks per matrix per stage, 4 per thread
    const int lrow[4] = { (t) >> 2, (t + 128) >> 2, (t + 256) >> 2, (t + 384) >> 2 };
    const int lci [4] = { (t) & 3,  (t + 128) & 3,  (t + 256) & 3,  (t + 384) & 3 };

    auto load_stage = [&](int st, int kt) {
        const int k0 = kt * 32;
        __nv_bfloat16* As = Asm + st * GSTAGE;
        __nv_bfloat16* Bs = Bsm + st * GSTAGE;
#pragma unroll
        for (int i = 0; i < 4; i++) {
            cpa16(&As[lrow[i] * GSTRIDE + lci[i] * 8],
                  &g_Vn[a_base + (size_t)lrow[i] * DQ + k0 + lci[i] * 8]);
            cpa16(&Bs[lrow[i] * GSTRIDE + lci[i] * 8],
                  &g_Ln[b_base + (size_t)lrow[i] * DQ + k0 + lci[i] * 8]);
        }
        CP_COMMIT();
    };

    const int NK = DQ / 32;           // 24
    load_stage(0, 0);
    load_stage(1, 1);

    for (int kt = 0; kt < NK; kt++) {
        const int cur = kt % 3;
        if (kt + 1 < NK) CP_WAIT(1); else CP_WAIT(0);
        __syncthreads();

        const __nv_bfloat16* As = Asm + cur * GSTAGE;
        const __nv_bfloat16* Bs = Bsm + cur * GSTAGE;
#pragma unroll
        for (int kk = 0; kk < 32; kk += 16) {
            unsigned af[4][4], bf[8][2];
            const int c = kk + tq * 2;
#pragma unroll
            for (int mi = 0; mi < 4; mi++) {
                int r = wm0 + mi * 16 + g;
                af[mi][0] = *(const unsigned*)&As[r * GSTRIDE + c];
                af[mi][1] = *(const unsigned*)&As[(r + 8) * GSTRIDE + c];
                af[mi][2] = *(const unsigned*)&As[r * GSTRIDE + c + 8];
                af[mi][3] = *(const unsigned*)&As[(r + 8) * GSTRIDE + c + 8];
            }
#pragma unroll
            for (int ni = 0; ni < 8; ni++) {
                int n = wn0 + ni * 8 + g;
                bf[ni][0] = *(const unsigned*)&Bs[n * GSTRIDE + c];
                bf[ni][1] = *(const unsigned*)&Bs[n * GSTRIDE + c + 8];
            }
#pragma unroll
            for (int mi = 0; mi < 4; mi++)
#pragma unroll
                for (int ni = 0; ni < 8; ni++) {
                    asm volatile(
                        "mma.sync.aligned.m16n8k16.row.col.f32.bf16.bf16.f32 "
                        "{%0,%1,%2,%3}, {%4,%5,%6,%7}, {%8,%9}, {%0,%1,%2,%3};\n"
                        : "+f"(acc[mi][ni][0]), "+f"(acc[mi][ni][1]),
                          "+f"(acc[mi][ni][2]), "+f"(acc[mi][ni][3])
                        : "r"(af[mi][0]), "r"(af[mi][1]), "r"(af[mi][2]), "r"(af[mi][3]),
                          "r"(bf[ni][0]), "r"(bf[ni][1]));
                }
        }
        // refill buffer (kt+2)%3: its last readers finished in iter kt-1,
        // ordered before this iteration's __syncthreads above.
        if (kt + 2 < NK) load_stage((kt + 2) % 3, kt + 2);
    }

    // per-row max over this 128-class tile
#pragma unroll
    for (int mi = 0; mi < 4; mi++) {
        float lo = -INFINITY, hi = -INFINITY;
#pragma unroll
        for (int ni = 0; ni < 8; ni++) {
            lo = fmaxf(lo, fmaxf(acc[mi][ni][0], acc[mi][ni][1]));
            hi = fmaxf(hi, fmaxf(acc[mi][ni][2], acc[mi][ni][3]));
        }
        lo = fmaxf(lo, __shfl_xor_sync(0xffffffffu, lo, 1));
        lo = fmaxf(lo, __shfl_xor_sync(0xffffffffu, lo, 2));
        hi = fmaxf(hi, __shfl_xor_sync(0xffffffffu, hi, 1));
        hi = fmaxf(hi, __shfl_xor_sync(0xffffffffu, hi, 2));
        if (tq == 0) {
            rmax[wm0 + mi * 16 + g][wc]     = lo;
            rmax[wm0 + mi * 16 + g + 8][wc] = hi;
        }
    }
    __syncthreads();
    if (t < 128) {
        float v = fmaxf(rmax[t][0], rmax[t][1]);
        atomicMax(&g_mkey[bm * 128 + t], enc_f(v));
    }
}

// ---------------- kernel 4a: softmax over S -> g_beta ----------------------
__global__ void beta_kernel() {
    __shared__ float red[16];
    const int b = blockIdx.x;
    const int t = threadIdx.x;
    const int lane = t & 31, wid = t >> 5;

    float m = dec_f(g_mkey[b * SQ + t]);
    float lm = m;
#pragma unroll
    for (int o = 16; o; o >>= 1) lm = fmaxf(lm, __shfl_xor_sync(0xffffffffu, lm, o));
    if (lane == 0) red[wid] = lm;
    __syncthreads();
    float M = red[0];
#pragma unroll
    for (int i = 1; i < 16; i++) M = fmaxf(M, red[i]);
    __syncthreads();

    float p = expf(m - M);
    float ls = p;
#pragma unroll
    for (int o = 16; o; o >>= 1) ls += __shfl_xor_sync(0xffffffffu, ls, o);
    if (lane == 0) red[wid] = ls;
    __syncthreads();
    float S = 0.f;
#pragma unroll
    for (int i = 0; i < 16; i++) S += red[i];

    g_beta[b * SQ + t] = p / S;
}

// ---------------- kernel 4b: partial z sums --------------------------------
__global__ void zpart_kernel(const float* __restrict__ V) {
    __shared__ float bsm[SQ / ZCH];
    const int b = blockIdx.x, ch = blockIdx.y;
    const int t = threadIdx.x;
    constexpr int RS = SQ / ZCH;   // 64 rows per chunk

    if (t < RS) bsm[t] = g_beta[b * SQ + ch * RS + t];
    __syncthreads();

    const float* Vb = V + ((size_t)b * SQ + ch * RS) * DQ;
    float a0 = 0.f, a1 = 0.f, a2 = 0.f;
#pragma unroll 4
    for (int r = 0; r < RS; r++) {
        float be = bsm[r];
        const float* row = Vb + (size_t)r * DQ;
        a0 += be * row[t];
        a1 += be * row[t + 256];
        a2 += be * row[t + 512];
    }
    float* zp = g_zpart + (size_t)(b * ZCH + ch) * DQ;
    zp[t]       = a0;
    zp[t + 256] = a1;
    zp[t + 512] = a2;
}

// ---------------- kernel 4c: combine partials -> z -------------------------
__global__ void zcombine_kernel(float* __restrict__ zout) {
    const int b = blockIdx.x;
    const int t = threadIdx.x;   // 256
#pragma unroll
    for (int j = 0; j < 3; j++) {
        int d = t + j * 256;
        float s = 0.f;
#pragma unroll
        for (int c = 0; c < ZCH; c++) s += g_zpart[(size_t)(b * ZCH + c) * DQ + d];
        g_z[b * DQ + d] = s;
        if (zout) zout[b * DQ + d] = s;
    }
}

// ---------------- kernel 5: out = z @ fc_w^T + fc_b ------------------------
__global__ void fc_kernel(const float* __restrict__ fc_w, const float* __restrict__ fc_b,
                          float* __restrict__ out) {
    const int t = threadIdx.x;
    const int lane = t & 31;
    const int gw = (blockIdx.x * blockDim.x + t) >> 5;
    if (gw >= BQ * CQ) return;
    const int b = gw >> 9;
    const int c = gw & 511;
    const float4* wr = (const float4*)(fc_w + (size_t)c * DQ);
    const float4* zr = (const float4*)(g_z + b * DQ);
    float acc = 0.f;
#pragma unroll
    for (int i = 0; i < 6; i++) {
        float4 wv = wr[lane + i * 32];
        float4 zv = zr[lane + i * 32];
        acc += wv.x * zv.x + wv.y * zv.y + wv.z * zv.z + wv.w * zv.w;
    }
#pragma unroll
    for (int o = 16; o; o >>= 1) acc += __shfl_xor_sync(0xffffffffu, acc, o);
    if (lane == 0) out[b * CQ + c] = acc + fc_b[c];
}

// ---------------- launch ----------------------------------------------------
extern "C" void kernel_launch(void* const* d_in, const int* in_sizes, int n_in,
                              void* d_out, int out_size) {
    const float* V  = (const float*)d_in[0];
    const float* L  = (const float*)d_in[1];
    const float* fw = (const float*)d_in[2];
    const float* fb = (const float*)d_in[3];
    float* out = (float*)d_out;
    float* zout = (out_size >= BQ * CQ + BQ * DQ) ? (out + BQ * CQ) : nullptr;

    static int smem_set = 0;
    if (!smem_set) {
        cudaFuncSetAttribute(gemm_rowmax_kernel,
                             cudaFuncAttributeMaxDynamicSharedMemorySize, GK_SMEM);
        smem_set = 1;
    }

    row_normalize_kernel<<<CQ / 8, 256>>>(L, CQ, 0);
    row_normalize_kernel<<<MQ / 8, 256>>>(V, MQ, 1);
    gemm_rowmax_kernel<<<dim3(CQ / 128, MQ / 128), 128, GK_SMEM>>>();
    beta_kernel<<<BQ, SQ>>>();
    zpart_kernel<<<dim3(BQ, ZCH), 256>>>(V);
    zcombine_kernel<<<BQ, 256>>>(zout);
    fc_kernel<<<(BQ * CQ * 32) / 256, 256>>>(fw, fb, out);
}